// round 10
// baseline (speedup 1.0000x reference)
#include <cuda_runtime.h>

#define N_GAUSS 4096
#define N_PTS 32768
#define NCELL 4096               /* 16^3 grid, cell side 0.5 over [-4,4], x-fastest */

typedef unsigned long long u64;

// fixed-point scale 2^45
#define FPSCALE 35184372088832.0
#define FPINV   (1.0 / 35184372088832.0)

__device__ float4 g_prm[N_GAUSS * 7];          // per-gaussian params (see prep)
__device__ int    g_off[NCELL];                // cell start in sorted order
__device__ int    g_ocnt[NCELL];               // cell count
__device__ int    g_perm[N_PTS];               // sorted slot -> original point
__device__ float4 g_spts[N_PTS];               // sorted NEGATED points
__device__ u64    g_acc[2 * N_PTS];            // fixed-point sums (zero-init; finalize re-zeros)

__device__ __forceinline__ float ex2f(float x) {
    float y; asm("ex2.approx.ftz.f32 %0, %1;" : "=f"(y) : "f"(x)); return y;
}
__device__ __forceinline__ float rsqf(float x) {
    float y; asm("rsqrt.approx.ftz.f32 %0, %1;" : "=f"(y) : "f"(x)); return y;
}
__device__ __forceinline__ int cellof(float v) {
    return min(15, max(0, (int)floorf((v + 4.f) * 2.f)));
}

// ---------------------------------------------------------------------------
// K1: per-gaussian preprocessing.
//  g_prm[g*7+0] = (gx, gy, gz, T)            T = 230*smax^2 (exact-zero cull radius^2)
//  [1] = (kP0, kP1, kP2, kP3)   precision * -0.5*log2(e), off-diagonals doubled
//  [2] = (kP4, kP5, op, c0)
//  [3..6] = c1..c15 (SH coefficients with basis constants folded), last slot pad
// n2 >= T  =>  exp(-0.5*maha) == +0.0f exactly (in the fp32 reference too).
// ---------------------------------------------------------------------------
__global__ void prep_kernel(const float* __restrict__ xyz,
                            const float* __restrict__ sh_dc,
                            const float* __restrict__ sh_rest,
                            const float* __restrict__ scaling,
                            const float* __restrict__ rotation,
                            const float* __restrict__ opacity) {
    int g = blockIdx.x * blockDim.x + threadIdx.x;
    if (g >= N_GAUSS) return;

    float qr = rotation[g*4+0], qx = rotation[g*4+1];
    float qy = rotation[g*4+2], qz = rotation[g*4+3];
    float qn = rsqrtf(qr*qr + qx*qx + qy*qy + qz*qz);
    qr *= qn; qx *= qn; qy *= qn; qz *= qn;

    float R00 = 1.f - 2.f*(qy*qy + qz*qz), R01 = 2.f*(qx*qy - qr*qz), R02 = 2.f*(qx*qz + qr*qy);
    float R10 = 2.f*(qx*qy + qr*qz), R11 = 1.f - 2.f*(qx*qx + qz*qz), R12 = 2.f*(qy*qz - qr*qx);
    float R20 = 2.f*(qx*qz - qr*qy), R21 = 2.f*(qy*qz + qr*qx), R22 = 1.f - 2.f*(qx*qx + qy*qy);

    float s0 = expf(scaling[g*3+0]);
    float s1 = expf(scaling[g*3+1]);
    float s2 = expf(scaling[g*3+2]);
    float iv0 = 1.f/(s0*s0), iv1 = 1.f/(s1*s1), iv2 = 1.f/(s2*s2);
    float smax = fmaxf(s0, fmaxf(s1, s2));
    float T = 230.f * smax * smax;

    float Pxx = iv0*R00*R00 + iv1*R01*R01 + iv2*R02*R02;
    float Pyy = iv0*R10*R10 + iv1*R11*R11 + iv2*R12*R12;
    float Pzz = iv0*R20*R20 + iv1*R21*R21 + iv2*R22*R22;
    float Pxy = iv0*R00*R10 + iv1*R01*R11 + iv2*R02*R12;
    float Pxz = iv0*R00*R20 + iv1*R01*R21 + iv2*R02*R22;
    float Pyz = iv0*R10*R20 + iv1*R11*R21 + iv2*R12*R22;

    const float kk = -0.7213475204444817f;  // -0.5 * log2(e)
    float op = 1.f / (1.f + expf(-opacity[g]));

    const float C0 = 0.28209479177387814f;
    const float C1 = 0.4886025119029199f;
    const float* sr = sh_rest + g*15;
    float c0  =  C0 * sh_dc[g];
    float c1  = -C1 * sr[0];
    float c2  =  C1 * sr[1];
    float c3  = -C1 * sr[2];
    float c4  =  1.0925484305920792f  * sr[3];
    float c5  = -1.0925484305920792f  * sr[4];
    float c6  =  0.31539156525252005f * sr[5];
    float c7  = -1.0925484305920792f  * sr[6];
    float c8  =  0.5462742152960396f  * sr[7];
    float c9  = -0.5900435899266435f  * sr[8];
    float c10 =  2.890611442640554f   * sr[9];
    float c11 = -0.4570457994644658f  * sr[10];
    float c12 =  0.3731763325901154f  * sr[11];
    float c13 = -0.4570457994644658f  * sr[12];
    float c14 =  1.445305721320277f   * sr[13];
    float c15 = -0.5900435899266435f  * sr[14];

    float4* o = &g_prm[g*7];
    o[0] = make_float4(xyz[g*3+0], xyz[g*3+1], xyz[g*3+2], T);
    o[1] = make_float4(kk*Pxx, kk*Pyy, kk*Pzz, 2.f*kk*Pxy);
    o[2] = make_float4(2.f*kk*Pxz, 2.f*kk*Pyz, op, c0);
    o[3] = make_float4(c1, c2, c3, c4);
    o[4] = make_float4(c5, c6, c7, c8);
    o[5] = make_float4(c9, c10, c11, c12);
    o[6] = make_float4(c13, c14, c15, 0.f);
}

// ---------------------------------------------------------------------------
// K2: fused count + scan + scatter, single CTA (one global-sync-free sort).
// Linear cell id (x fastest): c = ix + 16*iy + 256*iz, so an x-run of cells
// with fixed (iy,iz) is CONTIGUOUS in the sorted point array.
// Within-cell order from SMEM atomics is nondeterministic but harmless:
// per-point results are computed identically whichever slot/lane holds the
// point, excluded terms are exactly +0.0, and the u64 accumulation in K3 is
// order-invariant -> outputs are permutation-invariant.
// ---------------------------------------------------------------------------
__global__ void __launch_bounds__(1024) sort_kernel(const float* __restrict__ pts) {
    __shared__ int scnt[NCELL];     // counts, then reused as cursors
    __shared__ int ps[1024];
    int t = threadIdx.x;

#pragma unroll
    for (int k = 0; k < 4; ++k) scnt[t*4+k] = 0;
    __syncthreads();

    int cids[32];
#pragma unroll 4
    for (int k = 0; k < 32; ++k) {
        int i = t + k*1024;
        int c = cellof(pts[i*3+0]) | (cellof(pts[i*3+1]) << 4) | (cellof(pts[i*3+2]) << 8);
        cids[k] = c;
        atomicAdd(&scnt[c], 1);
    }
    __syncthreads();

    // exclusive scan over 4096 cells (4 per thread)
    int l0 = scnt[t*4+0], l1 = scnt[t*4+1], l2 = scnt[t*4+2], l3 = scnt[t*4+3];
    int s = l0 + l1 + l2 + l3;
    ps[t] = s; __syncthreads();
    for (int off = 1; off < 1024; off <<= 1) {
        int v = (t >= off) ? ps[t - off] : 0;
        __syncthreads();
        ps[t] += v;
        __syncthreads();
    }
    int run = ps[t] - s;
    g_off[t*4+0] = run; g_ocnt[t*4+0] = l0;
    int r1 = run + l0;
    g_off[t*4+1] = r1;  g_ocnt[t*4+1] = l1;
    int r2 = r1 + l1;
    g_off[t*4+2] = r2;  g_ocnt[t*4+2] = l2;
    int r3 = r2 + l2;
    g_off[t*4+3] = r3;  g_ocnt[t*4+3] = l3;
    __syncthreads();
    scnt[t*4+0] = run; scnt[t*4+1] = r1; scnt[t*4+2] = r2; scnt[t*4+3] = r3;
    __syncthreads();

#pragma unroll 4
    for (int k = 0; k < 32; ++k) {
        int i = t + k*1024;
        int slot = atomicAdd(&scnt[cids[k]], 1);
        g_perm[slot] = i;
        g_spts[slot] = make_float4(-pts[i*3+0], -pts[i*3+1], -pts[i*3+2], 0.f);
    }
}

// ---------------------------------------------------------------------------
// K3: gaussian-centric main. One WARP per gaussian; params live in registers.
// Warp scans only grid rows within reach (border-aware row cull), streams the
// contiguous x-run of sorted points (lane = point, coalesced), and for lanes
// with n2 < T adds fixed-point (2^-45) u64 terms atomically. Integer adds are
// associative -> bit-deterministic output for any arrival order.
// ---------------------------------------------------------------------------
__global__ void __launch_bounds__(128) main_kernel() {
    int warp = blockIdx.x * 4 + (threadIdx.x >> 5);   // gaussian id
    int lane = threadIdx.x & 31;

    const float4* P = &g_prm[warp*7];
    float4 a0 = __ldg(&P[0]);
    float4 a1 = __ldg(&P[1]);
    float4 a2 = __ldg(&P[2]);
    float4 a3 = __ldg(&P[3]);
    float4 a4 = __ldg(&P[4]);
    float4 a5 = __ldg(&P[5]);
    float4 a6 = __ldg(&P[6]);
    float gx = a0.x, gy = a0.y, gz = a0.z, T = a0.w;
    float R = sqrtf(T);

    int xlo = cellof(gx - R), xhi = cellof(gx + R);
    int ylo = cellof(gy - R), yhi = cellof(gy + R);
    int zlo = cellof(gz - R), zhi = cellof(gz + R);

    for (int iz = zlo; iz <= zhi; ++iz) {
        // border-aware z distance to row (border cells hold clamped outliers)
        float lz = (iz == 0)  ? -1e30f : iz*0.5f - 4.f;
        float hz = (iz == 15) ?  1e30f : iz*0.5f - 3.5f;
        float dz = fmaxf(0.f, fmaxf(lz - gz, gz - hz));
        for (int iy = ylo; iy <= yhi; ++iy) {
            float ly = (iy == 0)  ? -1e30f : iy*0.5f - 4.f;
            float hy = (iy == 15) ?  1e30f : iy*0.5f - 3.5f;
            float dy = fmaxf(0.f, fmaxf(ly - gy, gy - hy));
            if (dy*dy + dz*dz >= T) continue;     // row cannot contain a hit

            int cbase = (iy << 4) | (iz << 8);
            int cs = cbase + xlo, ce = cbase + xhi;
            int start = g_off[cs];
            int end   = g_off[ce] + g_ocnt[ce];

            for (int base = start; base < end; base += 32) {
                int i = base + lane;
                bool valid = i < end;
                float4 p = g_spts[valid ? i : start];    // negated point
                float ex = gx + p.x, ey = gy + p.y, ez = gz + p.z;  // g - pt
                float exx = ex*ex, eyy = ey*ey, ezz = ez*ez;
                float n2 = exx + eyy + ezz;
                bool act = valid && (n2 < T);
                if (!__ballot_sync(0xFFFFFFFFu, act)) continue;

                float pxy = ex*ey, pxz = ex*ez, pyz = ey*ez;
                // exponent (precision pre-scaled by -0.5*log2e, off-diag doubled)
                float m = exx*a1.x;
                m = fmaf(eyy, a1.y, m);
                m = fmaf(ezz, a1.z, m);
                m = fmaf(pxy, a1.w, m);
                m = fmaf(pxz, a2.x, m);
                m = fmaf(pyz, a2.y, m);
                float w = a2.z * ex2f(m);            // op * exp(-0.5*maha)

                // SH in e-space, Horner in rinv (validated R3-R7)
                float t6  = fmaf(3.f, ezz, -n2);
                float uq  = exx - eyy;
                float t9  = fmaf(3.f, exx, -eyy);
                float w5  = fmaf(5.f, ezz, -n2);
                float t12 = fmaf(-2.f, n2, w5);
                float t15 = fmaf(-3.f, ezz, uq);
                float S1 = fmaf(ex, a3.z, fmaf(ez, a3.y, ey*a3.x));
                float S2 = fmaf(uq, a4.w,
                           fmaf(pxz, a4.z,
                           fmaf(t6, a4.y,
                           fmaf(pyz, a4.x, pxy*a3.w))));
                float S3 = fmaf(ey*t9, a5.x,
                           fmaf(pxy*ez, a5.y,
                           fmaf(ey*w5, a5.z,
                           fmaf(ez*t12, a5.w,
                           fmaf(ex*w5, a6.x,
                           fmaf(ez*uq, a6.y, (ex*t15)*a6.z))))));
                float r = rsqf(n2);
                float res = fmaf(r, S3, S2);
                res = fmaf(r, res, S1);
                res = fmaf(r, res, a2.w);
                float mag = fmaxf(res, 0.f);

                if (act) {
                    u64 qw = __double2ull_rn((double)w * FPSCALE);
                    u64 qs = __double2ull_rn((double)(w * mag) * FPSCALE);
                    atomicAdd(&g_acc[i], qw);
                    atomicAdd(&g_acc[N_PTS + i], qs);
                }
            }
        }
    }
}

// ---------------------------------------------------------------------------
// K4: convert fixed-point sums to float, un-permute, and re-zero state for
// the next (graph-replayed) call.
// ---------------------------------------------------------------------------
__global__ void finalize_kernel(float* __restrict__ out) {
    int slot = blockIdx.x * blockDim.x + threadIdx.x;
    if (slot >= N_PTS) return;
    u64 aw = g_acc[slot];
    u64 as = g_acc[N_PTS + slot];
    int o = g_perm[slot];
    out[o]         = (float)((double)aw * FPINV);
    out[N_PTS + o] = (float)((double)as * FPINV);
    g_acc[slot] = 0ULL;
    g_acc[N_PTS + slot] = 0ULL;
}

extern "C" void kernel_launch(void* const* d_in, const int* in_sizes, int n_in,
                              void* d_out, int out_size) {
    const float* pts      = (const float*)d_in[0];  // network_pts
    // d_in[1] network_view, d_in[2] network_tx: unused by the reference math
    const float* xyz      = (const float*)d_in[3];
    const float* sh_dc    = (const float*)d_in[4];
    const float* sh_rest  = (const float*)d_in[5];
    const float* scaling  = (const float*)d_in[6];
    const float* rotation = (const float*)d_in[7];
    const float* opacity  = (const float*)d_in[8];

    prep_kernel<<<N_GAUSS/256, 256>>>(xyz, sh_dc, sh_rest, scaling, rotation, opacity);
    sort_kernel<<<1, 1024>>>(pts);
    main_kernel<<<N_GAUSS/4, 128>>>();
    finalize_kernel<<<N_PTS/256, 256>>>((float*)d_out);
}

// round 11
// speedup vs baseline: 1.0005x; 1.0005x over previous
#include <cuda_runtime.h>

#define N_GAUSS 4096
#define N_PTS 32768
#define NCELL 4096               /* 16^3 grid, cell side 0.5 over [-4,4], x-fastest */

typedef unsigned long long u64;

// fixed-point scale 2^45
#define FPSCALE 35184372088832.0
#define FPINV   (1.0 / 35184372088832.0)

__device__ float4 g_prm[N_GAUSS * 7];          // per-gaussian params (see prep)
__device__ int    g_off[NCELL];                // cell start in sorted order
__device__ int    g_ocnt[NCELL];               // cell count
__device__ int    g_perm[N_PTS];               // sorted slot -> original point
__device__ float4 g_spts[N_PTS];               // sorted NEGATED points
__device__ u64    g_acc[2 * N_PTS];            // fixed-point sums (zero-init; finalize re-zeros)

__device__ __forceinline__ float ex2f(float x) {
    float y; asm("ex2.approx.ftz.f32 %0, %1;" : "=f"(y) : "f"(x)); return y;
}
__device__ __forceinline__ float rsqf(float x) {
    float y; asm("rsqrt.approx.ftz.f32 %0, %1;" : "=f"(y) : "f"(x)); return y;
}
__device__ __forceinline__ int cellof(float v) {
    return min(15, max(0, (int)floorf((v + 4.f) * 2.f)));
}

// ---------------------------------------------------------------------------
// K1: per-gaussian preprocessing.
//  g_prm[g*7+0] = (gx, gy, gz, T)            T = 230*smax^2 (exact-zero cull radius^2)
//  [1] = (kP0, kP1, kP2, kP3)   precision * -0.5*log2(e), off-diagonals doubled
//  [2] = (kP4, kP5, op, c0)
//  [3..6] = c1..c15 (SH coefficients with basis constants folded), last slot pad
// n2 >= T  =>  exp(-0.5*maha) == +0.0f exactly (in the fp32 reference too).
// ---------------------------------------------------------------------------
__global__ void prep_kernel(const float* __restrict__ xyz,
                            const float* __restrict__ sh_dc,
                            const float* __restrict__ sh_rest,
                            const float* __restrict__ scaling,
                            const float* __restrict__ rotation,
                            const float* __restrict__ opacity) {
    int g = blockIdx.x * blockDim.x + threadIdx.x;
    if (g >= N_GAUSS) return;

    float qr = rotation[g*4+0], qx = rotation[g*4+1];
    float qy = rotation[g*4+2], qz = rotation[g*4+3];
    float qn = rsqrtf(qr*qr + qx*qx + qy*qy + qz*qz);
    qr *= qn; qx *= qn; qy *= qn; qz *= qn;

    float R00 = 1.f - 2.f*(qy*qy + qz*qz), R01 = 2.f*(qx*qy - qr*qz), R02 = 2.f*(qx*qz + qr*qy);
    float R10 = 2.f*(qx*qy + qr*qz), R11 = 1.f - 2.f*(qx*qx + qz*qz), R12 = 2.f*(qy*qz - qr*qx);
    float R20 = 2.f*(qx*qz - qr*qy), R21 = 2.f*(qy*qz + qr*qx), R22 = 1.f - 2.f*(qx*qx + qy*qy);

    float s0 = expf(scaling[g*3+0]);
    float s1 = expf(scaling[g*3+1]);
    float s2 = expf(scaling[g*3+2]);
    float iv0 = 1.f/(s0*s0), iv1 = 1.f/(s1*s1), iv2 = 1.f/(s2*s2);
    float smax = fmaxf(s0, fmaxf(s1, s2));
    float T = 230.f * smax * smax;

    float Pxx = iv0*R00*R00 + iv1*R01*R01 + iv2*R02*R02;
    float Pyy = iv0*R10*R10 + iv1*R11*R11 + iv2*R12*R12;
    float Pzz = iv0*R20*R20 + iv1*R21*R21 + iv2*R22*R22;
    float Pxy = iv0*R00*R10 + iv1*R01*R11 + iv2*R02*R12;
    float Pxz = iv0*R00*R20 + iv1*R01*R21 + iv2*R02*R22;
    float Pyz = iv0*R10*R20 + iv1*R11*R21 + iv2*R12*R22;

    const float kk = -0.7213475204444817f;  // -0.5 * log2(e)
    float op = 1.f / (1.f + expf(-opacity[g]));

    const float C0 = 0.28209479177387814f;
    const float C1 = 0.4886025119029199f;
    const float* sr = sh_rest + g*15;
    float c0  =  C0 * sh_dc[g];
    float c1  = -C1 * sr[0];
    float c2  =  C1 * sr[1];
    float c3  = -C1 * sr[2];
    float c4  =  1.0925484305920792f  * sr[3];
    float c5  = -1.0925484305920792f  * sr[4];
    float c6  =  0.31539156525252005f * sr[5];
    float c7  = -1.0925484305920792f  * sr[6];
    float c8  =  0.5462742152960396f  * sr[7];
    float c9  = -0.5900435899266435f  * sr[8];
    float c10 =  2.890611442640554f   * sr[9];
    float c11 = -0.4570457994644658f  * sr[10];
    float c12 =  0.3731763325901154f  * sr[11];
    float c13 = -0.4570457994644658f  * sr[12];
    float c14 =  1.445305721320277f   * sr[13];
    float c15 = -0.5900435899266435f  * sr[14];

    float4* o = &g_prm[g*7];
    o[0] = make_float4(xyz[g*3+0], xyz[g*3+1], xyz[g*3+2], T);
    o[1] = make_float4(kk*Pxx, kk*Pyy, kk*Pzz, 2.f*kk*Pxy);
    o[2] = make_float4(2.f*kk*Pxz, 2.f*kk*Pyz, op, c0);
    o[3] = make_float4(c1, c2, c3, c4);
    o[4] = make_float4(c5, c6, c7, c8);
    o[5] = make_float4(c9, c10, c11, c12);
    o[6] = make_float4(c13, c14, c15, 0.f);
}

// ---------------------------------------------------------------------------
// K2: fused count + scan + scatter, single CTA (one global-sync-free sort).
// Linear cell id (x fastest): c = ix + 16*iy + 256*iz, so an x-run of cells
// with fixed (iy,iz) is CONTIGUOUS in the sorted point array.
// Within-cell order from SMEM atomics is nondeterministic but harmless:
// per-point results are computed identically whichever slot/lane holds the
// point, excluded terms are exactly +0.0, and the u64 accumulation in K3 is
// order-invariant -> outputs are permutation-invariant.
// ---------------------------------------------------------------------------
__global__ void __launch_bounds__(1024) sort_kernel(const float* __restrict__ pts) {
    __shared__ int scnt[NCELL];     // counts, then reused as cursors
    __shared__ int ps[1024];
    int t = threadIdx.x;

#pragma unroll
    for (int k = 0; k < 4; ++k) scnt[t*4+k] = 0;
    __syncthreads();

    int cids[32];
#pragma unroll 4
    for (int k = 0; k < 32; ++k) {
        int i = t + k*1024;
        int c = cellof(pts[i*3+0]) | (cellof(pts[i*3+1]) << 4) | (cellof(pts[i*3+2]) << 8);
        cids[k] = c;
        atomicAdd(&scnt[c], 1);
    }
    __syncthreads();

    // exclusive scan over 4096 cells (4 per thread)
    int l0 = scnt[t*4+0], l1 = scnt[t*4+1], l2 = scnt[t*4+2], l3 = scnt[t*4+3];
    int s = l0 + l1 + l2 + l3;
    ps[t] = s; __syncthreads();
    for (int off = 1; off < 1024; off <<= 1) {
        int v = (t >= off) ? ps[t - off] : 0;
        __syncthreads();
        ps[t] += v;
        __syncthreads();
    }
    int run = ps[t] - s;
    g_off[t*4+0] = run; g_ocnt[t*4+0] = l0;
    int r1 = run + l0;
    g_off[t*4+1] = r1;  g_ocnt[t*4+1] = l1;
    int r2 = r1 + l1;
    g_off[t*4+2] = r2;  g_ocnt[t*4+2] = l2;
    int r3 = r2 + l2;
    g_off[t*4+3] = r3;  g_ocnt[t*4+3] = l3;
    __syncthreads();
    scnt[t*4+0] = run; scnt[t*4+1] = r1; scnt[t*4+2] = r2; scnt[t*4+3] = r3;
    __syncthreads();

#pragma unroll 4
    for (int k = 0; k < 32; ++k) {
        int i = t + k*1024;
        int slot = atomicAdd(&scnt[cids[k]], 1);
        g_perm[slot] = i;
        g_spts[slot] = make_float4(-pts[i*3+0], -pts[i*3+1], -pts[i*3+2], 0.f);
    }
}

// ---------------------------------------------------------------------------
// K3: gaussian-centric main. One WARP per gaussian; params live in registers.
// Warp scans only grid rows within reach (border-aware row cull), streams the
// contiguous x-run of sorted points (lane = point, coalesced), and for lanes
// with n2 < T adds fixed-point (2^-45) u64 terms atomically. Integer adds are
// associative -> bit-deterministic output for any arrival order.
// ---------------------------------------------------------------------------
__global__ void __launch_bounds__(128) main_kernel() {
    int warp = blockIdx.x * 4 + (threadIdx.x >> 5);   // gaussian id
    int lane = threadIdx.x & 31;

    const float4* P = &g_prm[warp*7];
    float4 a0 = __ldg(&P[0]);
    float4 a1 = __ldg(&P[1]);
    float4 a2 = __ldg(&P[2]);
    float4 a3 = __ldg(&P[3]);
    float4 a4 = __ldg(&P[4]);
    float4 a5 = __ldg(&P[5]);
    float4 a6 = __ldg(&P[6]);
    float gx = a0.x, gy = a0.y, gz = a0.z, T = a0.w;
    float R = sqrtf(T);

    int xlo = cellof(gx - R), xhi = cellof(gx + R);
    int ylo = cellof(gy - R), yhi = cellof(gy + R);
    int zlo = cellof(gz - R), zhi = cellof(gz + R);

    for (int iz = zlo; iz <= zhi; ++iz) {
        // border-aware z distance to row (border cells hold clamped outliers)
        float lz = (iz == 0)  ? -1e30f : iz*0.5f - 4.f;
        float hz = (iz == 15) ?  1e30f : iz*0.5f - 3.5f;
        float dz = fmaxf(0.f, fmaxf(lz - gz, gz - hz));
        for (int iy = ylo; iy <= yhi; ++iy) {
            float ly = (iy == 0)  ? -1e30f : iy*0.5f - 4.f;
            float hy = (iy == 15) ?  1e30f : iy*0.5f - 3.5f;
            float dy = fmaxf(0.f, fmaxf(ly - gy, gy - hy));
            if (dy*dy + dz*dz >= T) continue;     // row cannot contain a hit

            int cbase = (iy << 4) | (iz << 8);
            int cs = cbase + xlo, ce = cbase + xhi;
            int start = g_off[cs];
            int end   = g_off[ce] + g_ocnt[ce];

            for (int base = start; base < end; base += 32) {
                int i = base + lane;
                bool valid = i < end;
                float4 p = g_spts[valid ? i : start];    // negated point
                float ex = gx + p.x, ey = gy + p.y, ez = gz + p.z;  // g - pt
                float exx = ex*ex, eyy = ey*ey, ezz = ez*ez;
                float n2 = exx + eyy + ezz;
                bool act = valid && (n2 < T);
                if (!__ballot_sync(0xFFFFFFFFu, act)) continue;

                float pxy = ex*ey, pxz = ex*ez, pyz = ey*ez;
                // exponent (precision pre-scaled by -0.5*log2e, off-diag doubled)
                float m = exx*a1.x;
                m = fmaf(eyy, a1.y, m);
                m = fmaf(ezz, a1.z, m);
                m = fmaf(pxy, a1.w, m);
                m = fmaf(pxz, a2.x, m);
                m = fmaf(pyz, a2.y, m);
                float w = a2.z * ex2f(m);            // op * exp(-0.5*maha)

                // SH in e-space, Horner in rinv (validated R3-R7)
                float t6  = fmaf(3.f, ezz, -n2);
                float uq  = exx - eyy;
                float t9  = fmaf(3.f, exx, -eyy);
                float w5  = fmaf(5.f, ezz, -n2);
                float t12 = fmaf(-2.f, n2, w5);
                float t15 = fmaf(-3.f, ezz, uq);
                float S1 = fmaf(ex, a3.z, fmaf(ez, a3.y, ey*a3.x));
                float S2 = fmaf(uq, a4.w,
                           fmaf(pxz, a4.z,
                           fmaf(t6, a4.y,
                           fmaf(pyz, a4.x, pxy*a3.w))));
                float S3 = fmaf(ey*t9, a5.x,
                           fmaf(pxy*ez, a5.y,
                           fmaf(ey*w5, a5.z,
                           fmaf(ez*t12, a5.w,
                           fmaf(ex*w5, a6.x,
                           fmaf(ez*uq, a6.y, (ex*t15)*a6.z))))));
                float r = rsqf(n2);
                float res = fmaf(r, S3, S2);
                res = fmaf(r, res, S1);
                res = fmaf(r, res, a2.w);
                float mag = fmaxf(res, 0.f);

                if (act) {
                    u64 qw = __double2ull_rn((double)w * FPSCALE);
                    u64 qs = __double2ull_rn((double)(w * mag) * FPSCALE);
                    atomicAdd(&g_acc[i], qw);
                    atomicAdd(&g_acc[N_PTS + i], qs);
                }
            }
        }
    }
}

// ---------------------------------------------------------------------------
// K4: convert fixed-point sums to float, un-permute, and re-zero state for
// the next (graph-replayed) call.
// ---------------------------------------------------------------------------
__global__ void finalize_kernel(float* __restrict__ out) {
    int slot = blockIdx.x * blockDim.x + threadIdx.x;
    if (slot >= N_PTS) return;
    u64 aw = g_acc[slot];
    u64 as = g_acc[N_PTS + slot];
    int o = g_perm[slot];
    out[o]         = (float)((double)aw * FPINV);
    out[N_PTS + o] = (float)((double)as * FPINV);
    g_acc[slot] = 0ULL;
    g_acc[N_PTS + slot] = 0ULL;
}

extern "C" void kernel_launch(void* const* d_in, const int* in_sizes, int n_in,
                              void* d_out, int out_size) {
    const float* pts      = (const float*)d_in[0];  // network_pts
    // d_in[1] network_view, d_in[2] network_tx: unused by the reference math
    const float* xyz      = (const float*)d_in[3];
    const float* sh_dc    = (const float*)d_in[4];
    const float* sh_rest  = (const float*)d_in[5];
    const float* scaling  = (const float*)d_in[6];
    const float* rotation = (const float*)d_in[7];
    const float* opacity  = (const float*)d_in[8];

    prep_kernel<<<N_GAUSS/256, 256>>>(xyz, sh_dc, sh_rest, scaling, rotation, opacity);
    sort_kernel<<<1, 1024>>>(pts);
    main_kernel<<<N_GAUSS/4, 128>>>();
    finalize_kernel<<<N_PTS/256, 256>>>((float*)d_out);
}